// round 3
// baseline (speedup 1.0000x reference)
#include <cuda_runtime.h>

#define WI 512
#define HI 512
#define BN 8
#define CN 8
#define HW (HI * WI)

// Scratch accumulators (no device allocation allowed).
__device__ double g_big;    // sum over B*C*H*W terms (weights 0.2/0.8 applied)
__device__ double g_small;  // sum over B*1*H*W terms (bce1 + de2)

__device__ __forceinline__ float sigf(float x) {
    // 1 / (1 + e^-x): MUFU.EX2 + MUFU.RCP
    return __fdividef(1.0f, 1.0f + __expf(-x));
}

__device__ __forceinline__ float clog(float x) {
    // torch BCE clamps log at -100; __logf(0) = -inf -> clamp handles it
    return fmaxf(__logf(x), -100.0f);
}

// sigmoid of neighbor value; shifts zero-pad the PROBABILITY -> OOB = 0.0
__device__ __forceinline__ float nbr(const float* __restrict__ plane, int r, int w) {
    if ((unsigned)r >= (unsigned)HI || (unsigned)w >= (unsigned)WI) return 0.0f;
    return sigf(__ldg(plane + r * WI + w));
}

// Compute center probs p[8] and votes v[8] for one branch at pixel (r,w).
// vote_out order [a7,a3,a5,a1,a2,a6,a4,a8] maps exactly to
// v[ch] = p[ch] * sigmoid(channel (7-ch) at its shifted location).
__device__ __forceinline__ void branch_votes(
    const float* __restrict__ base, int r, int w, int off,
    float p[8], float v[8])
{
#pragma unroll
    for (int ch = 0; ch < 8; ch++)
        p[ch] = sigf(__ldg(base + ch * HW + off));
    float n7 = nbr(base + 7 * HW, r - 1, w - 1);
    float n6 = nbr(base + 6 * HW, r - 1, w);
    float n5 = nbr(base + 5 * HW, r - 1, w + 1);
    float n4 = nbr(base + 4 * HW, r,     w - 1);
    float n3 = nbr(base + 3 * HW, r,     w + 1);
    float n2 = nbr(base + 2 * HW, r + 1, w - 1);
    float n1 = nbr(base + 1 * HW, r + 1, w);
    float n0 = nbr(base + 0 * HW, r + 1, w + 1);
    v[0] = p[0] * n7;  // a7 = c0 * c7[r-1,w-1]
    v[1] = p[1] * n6;  // a3 = c1 * c6[r-1,w]
    v[2] = p[2] * n5;  // a5 = c2 * c5[r-1,w+1]
    v[3] = p[3] * n4;  // a1 = c3 * c4[r,w-1]
    v[4] = p[4] * n3;  // a2 = c4 * c3[r,w+1]
    v[5] = p[5] * n2;  // a6 = c5 * c2[r+1,w-1]
    v[6] = p[6] * n1;  // a4 = c6 * c1[r+1,w]
    v[7] = p[7] * n0;  // a8 = c7 * c0[r+1,w+1]
}

__global__ void init_k() {
    g_big = 0.0;
    g_small = 0.0;
}

__global__ void __launch_bounds__(256) loss_k(
    const float* __restrict__ atts, const float* __restrict__ dets,
    const float* __restrict__ target, const float* __restrict__ con)
{
    int idx = blockIdx.x * blockDim.x + threadIdx.x;  // [0, B*H*W)
    int w = idx & (WI - 1);
    int r = (idx >> 9) & (HI - 1);
    int b = idx >> 18;
    int off = r * WI + w;

    const float* A = atts + (size_t)b * CN * HW;
    const float* D = dets + (size_t)b * CN * HW;
    const float* C = con  + (size_t)b * CN * HW;

    float pa[8], pd[8], v1[8], v2[8];
    branch_votes(A, r, w, off, pa, v1);
    branch_votes(D, r, w, off, pd, v2);

    float big = 0.0f;
    float g1 = 0.0f, g2 = 0.0f, s = 0.0f, vmin = 2.0f;
#pragma unroll
    for (int ch = 0; ch < 8; ch++) {
        float t = __ldg(C + ch * HW + off);  // binary 0/1
        s += t;
        bool tt = t > 0.5f;
        // targets binary: BCE term collapses to one selected log
        big += 0.8f * clog(tt ? pa[ch] : 1.0f - pa[ch]);  // conn_loss1
        big += 0.2f * clog(tt ? v1[ch] : 1.0f - v1[ch]);  // bicon_loss1
        big += 0.8f * clog(tt ? pd[ch] : 1.0f - pd[ch]);  // conn_loss2
        big += 0.2f * clog(tt ? v2[ch] : 1.0f - v2[ch]);  // bicon_loss2
        g1 += v1[ch];
        g2 += v2[ch];
        vmin = fminf(vmin, v2[ch]);
    }
    g1 *= 0.125f;  // glo_map1
    g2 *= 0.125f;  // glo_map2

    float tg = __ldg(target + (size_t)b * HW + off);
    bool tt = tg > 0.5f;

    float small = clog(tt ? g1 : 1.0f - g1);  // bce_loss1

    // edge = 0 < sum(con) < 8 (sums are exact small integers)
    bool edge = (s > 0.5f) && (s < 7.5f);
    float dec = edge ? (1.0f - vmin) : g2;    // decouple_map
    small += clog(tt ? dec : 1.0f - dec);     // de_loss2

    // ---- block reduction (two floats) ----
#pragma unroll
    for (int o = 16; o > 0; o >>= 1) {
        big   += __shfl_down_sync(0xffffffffu, big, o);
        small += __shfl_down_sync(0xffffffffu, small, o);
    }
    __shared__ float sb[8], ss[8];
    int lane = threadIdx.x & 31;
    int wid  = threadIdx.x >> 5;
    if (lane == 0) { sb[wid] = big; ss[wid] = small; }
    __syncthreads();
    if (wid == 0) {
        big   = (lane < 8) ? sb[lane] : 0.0f;
        small = (lane < 8) ? ss[lane] : 0.0f;
#pragma unroll
        for (int o = 4; o > 0; o >>= 1) {
            big   += __shfl_down_sync(0xffffffffu, big, o);
            small += __shfl_down_sync(0xffffffffu, small, o);
        }
        if (lane == 0) {
            atomicAdd(&g_big,   (double)big);
            atomicAdd(&g_small, (double)small);
        }
    }
}

__global__ void fin_k(float* out) {
    const double N8 = (double)BN * CN * HW;  // 16777216
    const double N1 = (double)BN * HW;       // 2097152
    out[0] = (float)(-(g_big / N8) - (g_small / N1));
}

extern "C" void kernel_launch(void* const* d_in, const int* in_sizes, int n_in,
                              void* d_out, int out_size) {
    const float* atts   = (const float*)d_in[0];
    const float* dets   = (const float*)d_in[1];
    const float* target = (const float*)d_in[2];
    const float* con    = (const float*)d_in[3];
    float* out = (float*)d_out;

    init_k<<<1, 1>>>();
    int npix = BN * HW;  // 2,097,152
    loss_k<<<npix / 256, 256>>>(atts, dets, target, con);
    fin_k<<<1, 1>>>(out);
}